// round 8
// baseline (speedup 1.0000x reference)
#include <cuda_runtime.h>
#include <math.h>

#define B_   32
#define TT_  512
#define TM_  2048
#define D_   512
#define M_   80
#define NEGF (-1e9f)

#define HEXP_ELEMS (B_*TM_*D_)       /* 33554432 */
#define LOSS_OFF   HEXP_ELEMS
#define DUR_OFF    (HEXP_ELEMS + 1)

typedef unsigned long long ull;

// ------------------- device scratch (no allocation allowed) -------------------
__device__ float g_hw[B_*TT_*M_];         // [b*Tt+i][80] = h @ W
__device__ float g_hb[B_*TT_];            // h @ b_proj
__device__ float g_S[(size_t)B_*TM_*TT_]; // [b][j][i] masked scores (128 MB)
__device__ int   g_idx[B_*TM_];           // frame -> token index
__device__ float g_lsq[B_];
__device__ float g_lcnt[B_];

// ------------------- f32x2 helpers -------------------
__device__ __forceinline__ ull pk2(float x, float y) {
    ull r;
    asm("mov.b64 %0, {%1,%2};" : "=l"(r) : "f"(x), "f"(y));
    return r;
}
__device__ __forceinline__ float2 upk2(ull v) {
    float2 r;
    asm("mov.b64 {%0,%1}, %2;" : "=f"(r.x), "=f"(r.y) : "l"(v));
    return r;
}
#define FMA2(d, a, b, c) asm("fma.rn.f32x2 %0, %1, %2, %3;" : "=l"(d) : "l"(a), "l"(b), "l"(c))

// =================== K1: hw[b,i,m] = sum_d h[b,i,d] * w[d,m]  (R5, unchanged) ===================
__global__ void __launch_bounds__(256) k1_hw(const float* __restrict__ h,
                                             const float* __restrict__ w) {
    __shared__ float hS[64*68];   // [r][d] stride 68
    __shared__ float wS[64*84];   // [d][m] stride 84
    int tid  = threadIdx.x;
    int row0 = blockIdx.x * 64;
    int tx = tid & 15;
    int ty = tid >> 4;
    float acc[4][5];
#pragma unroll
    for (int r = 0; r < 4; r++)
#pragma unroll
        for (int m = 0; m < 5; m++) acc[r][m] = 0.f;

    for (int dc = 0; dc < D_; dc += 64) {
#pragma unroll
        for (int k = 0; k < 4; k++) {
            int l = tid + k*256;
            int r = l >> 4, d4 = l & 15;
            float4 v = *(const float4*)&h[(size_t)(row0 + r)*D_ + dc + d4*4];
            *(float4*)&hS[r*68 + d4*4] = v;
        }
#pragma unroll
        for (int k = 0; k < 5; k++) {
            int l = tid + k*256;
            int d = l / 20, m4 = l % 20;
            float4 v = *(const float4*)&w[(size_t)(dc + d)*M_ + m4*4];
            *(float4*)&wS[d*84 + m4*4] = v;
        }
        __syncthreads();
#pragma unroll 8
        for (int d = 0; d < 64; d++) {
            float a0 = hS[(ty*4+0)*68 + d];
            float a1 = hS[(ty*4+1)*68 + d];
            float a2 = hS[(ty*4+2)*68 + d];
            float a3 = hS[(ty*4+3)*68 + d];
#pragma unroll
            for (int m = 0; m < 5; m++) {
                float bv = wS[d*84 + tx*5 + m];
                acc[0][m] += a0*bv; acc[1][m] += a1*bv;
                acc[2][m] += a2*bv; acc[3][m] += a3*bv;
            }
        }
        __syncthreads();
    }
#pragma unroll
    for (int r = 0; r < 4; r++)
#pragma unroll
        for (int m = 0; m < 5; m++)
            g_hw[(size_t)(row0 + ty*4 + r)*M_ + tx*5 + m] = acc[r][m];
}

// =================== K1b: hb[row] = h[row,:] . b_proj  (R5, unchanged) ===================
__global__ void k1_hb(const float* __restrict__ h, const float* __restrict__ bp) {
    int gw   = (blockIdx.x*blockDim.x + threadIdx.x) >> 5;
    int lane = threadIdx.x & 31;
    if (gw >= B_*TT_) return;
    const float4* hr = (const float4*)&h[(size_t)gw * D_];
    const float4* b4 = (const float4*)bp;
    float s = 0.f;
    for (int k = lane; k < D_/4; k += 32) {
        float4 a = hr[k], c = b4[k];
        s += a.x*c.x + a.y*c.y + a.z*c.z + a.w*c.w;
    }
#pragma unroll
    for (int o = 16; o; o >>= 1) s += __shfl_down_sync(0xffffffffu, s, o);
    if (lane == 0) g_hb[gw] = s;
}

// =================== K2: S[b][j][i] = masked(hw . mel + hb)  (R5, unchanged) ===================
__global__ void __launch_bounds__(256) k2_attn(const float* __restrict__ mel,
                                               const int* __restrict__ tlv,
                                               const int* __restrict__ mlv) {
    extern __shared__ float sm2[];
    float* melS = sm2;            // [80][132]
    float* hwS  = sm2 + 80*132;   // [80][129]
    int b  = blockIdx.z;
    int ml = mlv[b];
    int j0 = blockIdx.y * 128;
    if (j0 >= ml) return;
    int i0  = blockIdx.x * 128;
    int tid = threadIdx.x;
    int tx  = tid & 15;
    int ty  = tid >> 4;

    const float* melB = mel + (size_t)b*M_*TM_;
#pragma unroll
    for (int k = 0; k < 10; k++) {
        int l = tid + k*256;
        int m = l >> 5, j4 = l & 31;
        float4 v = *(const float4*)&melB[(size_t)m*TM_ + j0 + j4*4];
        *(float4*)&melS[m*132 + j4*4] = v;
    }
    const float* hwB = g_hw + (size_t)b*TT_*M_;
#pragma unroll
    for (int k = 0; k < 40; k++) {
        int l = tid + k*256;
        int m = l % 80, ii = l / 80;
        hwS[m*129 + ii] = hwB[(size_t)(i0+ii)*M_ + m];
    }
    __syncthreads();

    ull acc[8][4];
#pragma unroll
    for (int jk = 0; jk < 8; jk++)
#pragma unroll
        for (int p = 0; p < 4; p++) acc[jk][p] = 0ull;

#pragma unroll 2
    for (int m = 0; m < M_; m++) {
        float hv[8];
#pragma unroll
        for (int k = 0; k < 8; k++) hv[k] = hwS[m*129 + tx + 16*k];
        ull hp[4];
#pragma unroll
        for (int p = 0; p < 4; p++) hp[p] = pk2(hv[2*p], hv[2*p+1]);
#pragma unroll
        for (int jk = 0; jk < 8; jk++) {
            float mv = melS[m*132 + ty + 16*jk];
            ull mp = pk2(mv, mv);
#pragma unroll
            for (int p = 0; p < 4; p++) FMA2(acc[jk][p], hp[p], mp, acc[jk][p]);
        }
    }

    int tlb = tlv[b];
    float hbv[8];
    bool  msk[8];
#pragma unroll
    for (int k = 0; k < 8; k++) {
        int ig = i0 + tx + 16*k;
        hbv[k] = g_hb[b*TT_ + ig];
        msk[k] = (ig < tlb);
    }
#pragma unroll
    for (int jk = 0; jk < 8; jk++) {
        int j = j0 + ty + 16*jk;
        if (j < ml) {
            float* row = g_S + ((size_t)b*TM_ + j)*TT_ + i0;
#pragma unroll
            for (int p = 0; p < 4; p++) {
                float2 v = upk2(acc[jk][p]);
                int k0 = 2*p, k1 = 2*p + 1;
                row[tx + 16*k0] = msk[k0] ? (v.x + hbv[k0]) : NEGF;
                row[tx + 16*k1] = msk[k1] ? (v.y + hbv[k1]) : NEGF;
            }
        }
    }
}

// =================== K3: MAS DP — warp-per-batch, 16 rows/thread, no barriers ===================
// grid 32 (one block/batch), 32 threads. Lane l owns rows [16l, 16l+15].
// Per column: 1 shfl_up (boundary row) + 16 independent row updates. Choice bits
// accumulate in registers, flushed to smem every 32 columns. 8-column register
// prefetch ring covers DRAM latency of the S stream.
__global__ void __launch_bounds__(32) k3_dp(const float* __restrict__ ldp,
                                            const int* __restrict__ tlv,
                                            const int* __restrict__ mlv,
                                            float* __restrict__ out) {
    extern __shared__ unsigned int dsm3[];
    unsigned int* ch  = dsm3;            // [512][65] choice bits (stride 65)
    unsigned int* dur = dsm3 + 512*65;   // [512]

    int b    = blockIdx.x;
    int lane = threadIdx.x;
    int tl = tlv[b], ml = mlv[b];
    const float* Sb = g_S + (size_t)b*TM_*TT_;

    float q[16]; unsigned int cw[16];
#pragma unroll
    for (int r = 0; r < 16; r++) { q[r] = NEGF; cw[r] = 0u; }
    if (lane == 0) q[0] = Sb[0];

#pragma unroll
    for (int r = 0; r < 16; r++) dur[lane*16 + r] = 0u;

    // ---- 8-deep register prefetch ring: buf[u] holds column (groupbase + u) ----
    float4 buf[8][4];
#pragma unroll
    for (int u = 0; u < 8; u++) {
        int j = 1 + u;
        if (j < ml) {
            const float4* p = (const float4*)(Sb + (size_t)j*TT_) + lane*4;
            buf[u][0] = p[0]; buf[u][1] = p[1]; buf[u][2] = p[2]; buf[u][3] = p[3];
        }
    }

    int j = 1;
    while (j < ml) {
#pragma unroll
        for (int u = 0; u < 8; u++) {
            if (j < ml) {
                float bnd = __shfl_up_sync(0xffffffffu, q[15], 1);
                unsigned int mask = 1u << (j & 31);
                const float* cc = (const float*)&buf[u][0];
                // descending r: q[r-1] still holds the previous column's value
#pragma unroll
                for (int r = 15; r >= 1; r--) {
                    float qs = q[r-1];
                    if (qs > q[r]) cw[r] |= mask;
                    q[r] = cc[r] + fmaxf(q[r], qs);
                }
                {
                    float qs = (lane == 0) ? NEGF : bnd;
                    if (qs > q[0]) cw[0] |= mask;
                    q[0] = cc[0] + fmaxf(q[0], qs);
                }
                if ((j & 31) == 31) {
                    int w = j >> 5;
#pragma unroll
                    for (int r = 0; r < 16; r++) { ch[(lane*16 + r)*65 + w] = cw[r]; cw[r] = 0u; }
                }
                int jn = j + 8;                  // refill this slot
                if (jn < ml) {
                    const float4* p = (const float4*)(Sb + (size_t)jn*TT_) + lane*4;
                    buf[u][0] = p[0]; buf[u][1] = p[1]; buf[u][2] = p[2]; buf[u][3] = p[3];
                }
                j++;
            }
        }
    }
    if (((ml - 1) & 31) != 31) {
        int w = (ml - 1) >> 5;
#pragma unroll
        for (int r = 0; r < 16; r++) ch[(lane*16 + r)*65 + w] = cw[r];
    }
    __syncwarp();

    if (lane == 0) {                     // serial CLZ run-scan backtrack
        int ii = tl - 1, jj = ml - 1;
        while (jj >= 0) {
            if (ii == 0) { dur[0] += (unsigned)(jj + 1); break; }
            unsigned int wv = ch[ii*65 + (jj >> 5)];
            int bit = jj & 31;
            if (bit != 31) wv &= (2u << bit) - 1u;
            if (wv == 0) { dur[ii] += (unsigned)(bit + 1); jj -= bit + 1; }
            else {
                int hb = 31 - __clz(wv);
                int jp = (jj & ~31) + hb;
                dur[ii] += (unsigned)(jj - jp + 1);
                ii -= 1;
                jj = jp - 1;
            }
        }
    }
    __syncwarp();

    // ---- outputs: durations, loss partial, idx scatter ----
    unsigned int dv[16], tot = 0;
#pragma unroll
    for (int r = 0; r < 16; r++) { dv[r] = dur[lane*16 + r]; tot += dv[r]; }

    float ls = 0.f;
#pragma unroll
    for (int r = 0; r < 16; r++) {
        int row = lane*16 + r;
        out[DUR_OFF + b*TT_ + row] = (float)dv[r];
        if (row < tl) {
            float lg = logf(fmaxf((float)dv[r], 1.0f));
            float df = ldp[b*TT_ + row] - lg;
            ls += df * df;
        }
    }
#pragma unroll
    for (int o = 16; o; o >>= 1) ls += __shfl_down_sync(0xffffffffu, ls, o);
    if (lane == 0) { g_lsq[b] = ls; g_lcnt[b] = (float)tl; }

    unsigned int v = tot;
#pragma unroll
    for (int o = 1; o < 32; o <<= 1) {
        unsigned int t = __shfl_up_sync(0xffffffffu, v, o);
        if (lane >= o) v += t;
    }
    unsigned int pos = v - tot;          // exclusive prefix
#pragma unroll
    for (int r = 0; r < 16; r++) {
        int row = lane*16 + r;
        for (unsigned int k = 0; k < dv[r]; k++) g_idx[b*TM_ + pos + k] = row;
        pos += dv[r];
    }
}

// =================== K5: length-regulate expansion (+ fused loss reduce) ===================
__global__ void __launch_bounds__(256) k5_expand(const float* __restrict__ h,
                                                 const int* __restrict__ mlv,
                                                 float* __restrict__ out) {
    if (blockIdx.y == 0 && blockIdx.z == 0 && threadIdx.x < 32) {
        float s = g_lsq[threadIdx.x], cc = g_lcnt[threadIdx.x];
#pragma unroll
        for (int o = 16; o; o >>= 1) {
            s  += __shfl_down_sync(0xffffffffu, s, o);
            cc += __shfl_down_sync(0xffffffffu, cc, o);
        }
        if (threadIdx.x == 0) out[LOSS_OFF] = s / cc;
    }
    int b  = blockIdx.z;
    int j  = blockIdx.y * 2 + (threadIdx.x >> 7);
    int c4 = threadIdx.x & 127;
    int ml = mlv[b];
    float4 v;
    if (j < ml) {
        int idx = g_idx[b*TM_ + j];
        v = *(const float4*)&h[((size_t)(b*TT_ + idx))*D_ + c4*4];
    } else {
        v = make_float4(0.f, 0.f, 0.f, 0.f);
    }
    *(float4*)&out[((size_t)(b*TM_ + j))*D_ + c4*4] = v;
}

// =================== host launcher ===================
extern "C" void kernel_launch(void* const* d_in, const int* in_sizes, int n_in,
                              void* d_out, int out_size) {
    const float* h_text = (const float*)d_in[0];   // [32,512,512]
    const float* mel    = (const float*)d_in[1];   // [32,80,2048]
    const int*   tl     = (const int*)  d_in[2];   // [32]
    const int*   mlv    = (const int*)  d_in[3];   // [32]
    const float* w_proj = (const float*)d_in[4];   // [512,80]
    const float* b_proj = (const float*)d_in[5];   // [512]
    const float* ldp    = (const float*)d_in[6];   // [32,512]
    float* out = (float*)d_out;

    const int K2_SMEM = (80*132 + 80*129) * 4;        // 83520
    const int K3_SMEM = (512*65 + 512) * 4;           // 135168
    cudaFuncSetAttribute(k2_attn, cudaFuncAttributeMaxDynamicSharedMemorySize, K2_SMEM);
    cudaFuncSetAttribute(k3_dp,   cudaFuncAttributeMaxDynamicSharedMemorySize, K3_SMEM);

    k1_hw<<<256, 256>>>(h_text, w_proj);
    k1_hb<<<2048, 256>>>(h_text, b_proj);
    k2_attn<<<dim3(4, 16, 32), 256, K2_SMEM>>>(mel, tl, mlv);
    k3_dp<<<32, 32, K3_SMEM>>>(ldp, tl, mlv, out);
    k5_expand<<<dim3(1, 1024, 32), 256>>>(h_text, mlv, out);
}

// round 9
// speedup vs baseline: 2.2918x; 2.2918x over previous
#include <cuda_runtime.h>
#include <math.h>

#define B_   32
#define TT_  512
#define TM_  2048
#define D_   512
#define M_   80
#define NEGF (-1e9f)

#define HEXP_ELEMS (B_*TM_*D_)       /* 33554432 */
#define LOSS_OFF   HEXP_ELEMS
#define DUR_OFF    (HEXP_ELEMS + 1)

typedef unsigned long long ull;

// ------------------- device scratch (no allocation allowed) -------------------
__device__ float g_hw[B_*TT_*M_];         // [b*Tt+i][80] = h @ W
__device__ float g_hb[B_*TT_];            // h @ b_proj
__device__ float g_S[(size_t)B_*TM_*TT_]; // [b][j][i] masked scores (128 MB)
__device__ int   g_idx[B_*TM_];           // frame -> token index
__device__ float g_lsq[B_];
__device__ float g_lcnt[B_];

// ------------------- f32x2 helpers -------------------
__device__ __forceinline__ ull pk2(float x, float y) {
    ull r;
    asm("mov.b64 %0, {%1,%2};" : "=l"(r) : "f"(x), "f"(y));
    return r;
}
__device__ __forceinline__ float2 upk2(ull v) {
    float2 r;
    asm("mov.b64 {%0,%1}, %2;" : "=f"(r.x), "=f"(r.y) : "l"(v));
    return r;
}
#define FMA2(d, a, b, c) asm("fma.rn.f32x2 %0, %1, %2, %3;" : "=l"(d) : "l"(a), "l"(b), "l"(c))

// =================== K1: hw[b,i,m] = sum_d h[b,i,d] * w[d,m]  (R5, unchanged) ===================
__global__ void __launch_bounds__(256) k1_hw(const float* __restrict__ h,
                                             const float* __restrict__ w) {
    __shared__ float hS[64*68];   // [r][d] stride 68
    __shared__ float wS[64*84];   // [d][m] stride 84
    int tid  = threadIdx.x;
    int row0 = blockIdx.x * 64;
    int tx = tid & 15;
    int ty = tid >> 4;
    float acc[4][5];
#pragma unroll
    for (int r = 0; r < 4; r++)
#pragma unroll
        for (int m = 0; m < 5; m++) acc[r][m] = 0.f;

    for (int dc = 0; dc < D_; dc += 64) {
#pragma unroll
        for (int k = 0; k < 4; k++) {
            int l = tid + k*256;
            int r = l >> 4, d4 = l & 15;
            float4 v = *(const float4*)&h[(size_t)(row0 + r)*D_ + dc + d4*4];
            *(float4*)&hS[r*68 + d4*4] = v;
        }
#pragma unroll
        for (int k = 0; k < 5; k++) {
            int l = tid + k*256;
            int d = l / 20, m4 = l % 20;
            float4 v = *(const float4*)&w[(size_t)(dc + d)*M_ + m4*4];
            *(float4*)&wS[d*84 + m4*4] = v;
        }
        __syncthreads();
#pragma unroll 8
        for (int d = 0; d < 64; d++) {
            float a0 = hS[(ty*4+0)*68 + d];
            float a1 = hS[(ty*4+1)*68 + d];
            float a2 = hS[(ty*4+2)*68 + d];
            float a3 = hS[(ty*4+3)*68 + d];
#pragma unroll
            for (int m = 0; m < 5; m++) {
                float bv = wS[d*84 + tx*5 + m];
                acc[0][m] += a0*bv; acc[1][m] += a1*bv;
                acc[2][m] += a2*bv; acc[3][m] += a3*bv;
            }
        }
        __syncthreads();
    }
#pragma unroll
    for (int r = 0; r < 4; r++)
#pragma unroll
        for (int m = 0; m < 5; m++)
            g_hw[(size_t)(row0 + ty*4 + r)*M_ + tx*5 + m] = acc[r][m];
}

// =================== K1b: hb[row] = h[row,:] . b_proj  (R5, unchanged) ===================
__global__ void k1_hb(const float* __restrict__ h, const float* __restrict__ bp) {
    int gw   = (blockIdx.x*blockDim.x + threadIdx.x) >> 5;
    int lane = threadIdx.x & 31;
    if (gw >= B_*TT_) return;
    const float4* hr = (const float4*)&h[(size_t)gw * D_];
    const float4* b4 = (const float4*)bp;
    float s = 0.f;
    for (int k = lane; k < D_/4; k += 32) {
        float4 a = hr[k], c = b4[k];
        s += a.x*c.x + a.y*c.y + a.z*c.z + a.w*c.w;
    }
#pragma unroll
    for (int o = 16; o; o >>= 1) s += __shfl_down_sync(0xffffffffu, s, o);
    if (lane == 0) g_hb[gw] = s;
}

// =================== K2: S[b][j][i] = masked(hw . mel + hb)  (R5, unchanged) ===================
__global__ void __launch_bounds__(256) k2_attn(const float* __restrict__ mel,
                                               const int* __restrict__ tlv,
                                               const int* __restrict__ mlv) {
    extern __shared__ float sm2[];
    float* melS = sm2;            // [80][132]
    float* hwS  = sm2 + 80*132;   // [80][129]
    int b  = blockIdx.z;
    int ml = mlv[b];
    int j0 = blockIdx.y * 128;
    if (j0 >= ml) return;
    int i0  = blockIdx.x * 128;
    int tid = threadIdx.x;
    int tx  = tid & 15;
    int ty  = tid >> 4;

    const float* melB = mel + (size_t)b*M_*TM_;
#pragma unroll
    for (int k = 0; k < 10; k++) {
        int l = tid + k*256;
        int m = l >> 5, j4 = l & 31;
        float4 v = *(const float4*)&melB[(size_t)m*TM_ + j0 + j4*4];
        *(float4*)&melS[m*132 + j4*4] = v;
    }
    const float* hwB = g_hw + (size_t)b*TT_*M_;
#pragma unroll
    for (int k = 0; k < 40; k++) {
        int l = tid + k*256;
        int m = l % 80, ii = l / 80;
        hwS[m*129 + ii] = hwB[(size_t)(i0+ii)*M_ + m];
    }
    __syncthreads();

    ull acc[8][4];
#pragma unroll
    for (int jk = 0; jk < 8; jk++)
#pragma unroll
        for (int p = 0; p < 4; p++) acc[jk][p] = 0ull;

#pragma unroll 2
    for (int m = 0; m < M_; m++) {
        float hv[8];
#pragma unroll
        for (int k = 0; k < 8; k++) hv[k] = hwS[m*129 + tx + 16*k];
        ull hp[4];
#pragma unroll
        for (int p = 0; p < 4; p++) hp[p] = pk2(hv[2*p], hv[2*p+1]);
#pragma unroll
        for (int jk = 0; jk < 8; jk++) {
            float mv = melS[m*132 + ty + 16*jk];
            ull mp = pk2(mv, mv);
#pragma unroll
            for (int p = 0; p < 4; p++) FMA2(acc[jk][p], hp[p], mp, acc[jk][p]);
        }
    }

    int tlb = tlv[b];
    float hbv[8];
    bool  msk[8];
#pragma unroll
    for (int k = 0; k < 8; k++) {
        int ig = i0 + tx + 16*k;
        hbv[k] = g_hb[b*TT_ + ig];
        msk[k] = (ig < tlb);
    }
#pragma unroll
    for (int jk = 0; jk < 8; jk++) {
        int j = j0 + ty + 16*jk;
        if (j < ml) {
            float* row = g_S + ((size_t)b*TM_ + j)*TT_ + i0;
#pragma unroll
            for (int p = 0; p < 4; p++) {
                float2 v = upk2(acc[jk][p]);
                int k0 = 2*p, k1 = 2*p + 1;
                row[tx + 16*k0] = msk[k0] ? (v.x + hbv[k0]) : NEGF;
                row[tx + 16*k1] = msk[k1] ? (v.y + hbv[k1]) : NEGF;
            }
        }
    }
}

// =================== K3: MAS DP — single warp/batch, compile-safe ring ===================
// Lane l owns rows [16l, 16l+15]. Per column: 1 shfl (pipelined) + 16 independent
// row updates. Main loop: full 8-column groups, fully unrolled, refills ALWAYS
// execute (clamped address) so buf[] indexing is compile-time only -> registers.
// Choice bits: ch[w][r][lane] layout -> conflict-free flush stores.
__global__ void __launch_bounds__(32) k3_dp(const float* __restrict__ ldp,
                                            const int* __restrict__ tlv,
                                            const int* __restrict__ mlv,
                                            float* __restrict__ out) {
    extern __shared__ unsigned int dsm3[];
    unsigned int* ch  = dsm3;            // [64][16][32]: w, r, lane
    unsigned int* dur = dsm3 + 64*512;   // [512]

    int b    = blockIdx.x;
    int lane = threadIdx.x;
    int tl = tlv[b], ml = mlv[b];
    const float*  Sb  = g_S + (size_t)b*TM_*TT_;
    const float4* Sb4 = (const float4*)Sb;          // column j = Sb4 + j*128

    float q[16]; unsigned int cw[16];
#pragma unroll
    for (int r = 0; r < 16; r++) { q[r] = NEGF; cw[r] = 0u; }
    if (lane == 0) q[0] = Sb[0];

#pragma unroll
    for (int r = 0; r < 16; r++) dur[r*32 + lane] = 0u;

    // initial ring fill: columns 1..8 (ml >= 1024 always)
    float4 buf[8][4];
#pragma unroll
    for (int u = 0; u < 8; u++) {
        const float4* p = Sb4 + (size_t)(1 + u)*(TT_/4) + lane*4;
        buf[u][0] = p[0]; buf[u][1] = p[1]; buf[u][2] = p[2]; buf[u][3] = p[3];
    }

    int nfull = (ml - 1) >> 3;           // full 8-column groups
    int jlim  = ml - 1;
    for (int g = 0; g < nfull; g++) {
        int jbase = 1 + (g << 3);
#pragma unroll
        for (int u = 0; u < 8; u++) {
            int j = jbase + u;
            float bnd = __shfl_up_sync(0xffffffffu, q[15], 1);
            unsigned int mask = 1u << (j & 31);
            const float* cc = (const float*)buf[u];
#pragma unroll
            for (int r = 15; r >= 1; r--) {
                float qs = q[r-1];
                if (qs > q[r]) cw[r] |= mask;
                q[r] = cc[r] + fmaxf(q[r], qs);
            }
            {
                float qs = (lane == 0) ? NEGF : bnd;
                if (qs > q[0]) cw[0] |= mask;
                q[0] = cc[0] + fmaxf(q[0], qs);
            }
            if ((j & 31) == 31) {
                unsigned int* crow = ch + (j >> 5)*512 + lane;
#pragma unroll
                for (int r = 0; r < 16; r++) { crow[r*32] = cw[r]; cw[r] = 0u; }
            }
            // refill this slot for column j+8 (clamped; always executes)
            int jn = j + 8; if (jn > jlim) jn = jlim;
            const float4* p = Sb4 + (size_t)jn*(TT_/4) + lane*4;
            buf[u][0] = p[0]; buf[u][1] = p[1]; buf[u][2] = p[2]; buf[u][3] = p[3];
        }
    }
    // tail columns (< 8): direct loads
    for (int j = 1 + (nfull << 3); j < ml; j++) {
        float bnd = __shfl_up_sync(0xffffffffu, q[15], 1);
        unsigned int mask = 1u << (j & 31);
        const float4* p = Sb4 + (size_t)j*(TT_/4) + lane*4;
        float4 t0 = p[0], t1 = p[1], t2 = p[2], t3 = p[3];
        float cc[16] = {t0.x,t0.y,t0.z,t0.w, t1.x,t1.y,t1.z,t1.w,
                        t2.x,t2.y,t2.z,t2.w, t3.x,t3.y,t3.z,t3.w};
#pragma unroll
        for (int r = 15; r >= 1; r--) {
            float qs = q[r-1];
            if (qs > q[r]) cw[r] |= mask;
            q[r] = cc[r] + fmaxf(q[r], qs);
        }
        {
            float qs = (lane == 0) ? NEGF : bnd;
            if (qs > q[0]) cw[0] |= mask;
            q[0] = cc[0] + fmaxf(q[0], qs);
        }
        if ((j & 31) == 31) {
            unsigned int* crow = ch + (j >> 5)*512 + lane;
#pragma unroll
            for (int r = 0; r < 16; r++) { crow[r*32] = cw[r]; cw[r] = 0u; }
        }
    }
    if (((ml - 1) & 31) != 31) {
        unsigned int* crow = ch + ((ml - 1) >> 5)*512 + lane;
#pragma unroll
        for (int r = 0; r < 16; r++) crow[r*32] = cw[r];
    }
    __syncwarp();

    if (lane == 0) {                     // serial CLZ run-scan backtrack
        int ii = tl - 1, jj = ml - 1;
        while (jj >= 0) {
            if (ii == 0) { dur[0] += (unsigned)(jj + 1); break; }
            unsigned int wv = ch[(jj >> 5)*512 + (ii & 15)*32 + (ii >> 4)];
            int bit = jj & 31;
            if (bit != 31) wv &= (2u << bit) - 1u;
            if (wv == 0) { dur[(ii & 15)*32 + (ii >> 4)] += (unsigned)(bit + 1); jj -= bit + 1; }
            else {
                int hb = 31 - __clz(wv);
                int jp = (jj & ~31) + hb;
                dur[(ii & 15)*32 + (ii >> 4)] += (unsigned)(jj - jp + 1);
                ii -= 1;
                jj = jp - 1;
            }
        }
    }
    __syncwarp();

    // ---- outputs: durations, loss partial, idx scatter ----
    unsigned int dv[16], tot = 0;
#pragma unroll
    for (int r = 0; r < 16; r++) { dv[r] = dur[r*32 + lane]; tot += dv[r]; }

    float ls = 0.f;
#pragma unroll
    for (int r = 0; r < 16; r++) {
        int row = lane*16 + r;
        out[DUR_OFF + b*TT_ + row] = (float)dv[r];
        if (row < tl) {
            float lg = logf(fmaxf((float)dv[r], 1.0f));
            float df = ldp[b*TT_ + row] - lg;
            ls += df * df;
        }
    }
#pragma unroll
    for (int o = 16; o; o >>= 1) ls += __shfl_down_sync(0xffffffffu, ls, o);
    if (lane == 0) { g_lsq[b] = ls; g_lcnt[b] = (float)tl; }

    unsigned int v = tot;
#pragma unroll
    for (int o = 1; o < 32; o <<= 1) {
        unsigned int t = __shfl_up_sync(0xffffffffu, v, o);
        if (lane >= o) v += t;
    }
    unsigned int pos = v - tot;          // exclusive prefix over lanes
#pragma unroll
    for (int r = 0; r < 16; r++) {
        int row = lane*16 + r;
        for (unsigned int k = 0; k < dv[r]; k++) g_idx[b*TM_ + pos + k] = row;
        pos += dv[r];
    }
}

// =================== K5: length-regulate expansion (+ fused loss reduce) ===================
__global__ void __launch_bounds__(256) k5_expand(const float* __restrict__ h,
                                                 const int* __restrict__ mlv,
                                                 float* __restrict__ out) {
    if (blockIdx.y == 0 && blockIdx.z == 0 && threadIdx.x < 32) {
        float s = g_lsq[threadIdx.x], cc = g_lcnt[threadIdx.x];
#pragma unroll
        for (int o = 16; o; o >>= 1) {
            s  += __shfl_down_sync(0xffffffffu, s, o);
            cc += __shfl_down_sync(0xffffffffu, cc, o);
        }
        if (threadIdx.x == 0) out[LOSS_OFF] = s / cc;
    }
    int b  = blockIdx.z;
    int j  = blockIdx.y * 2 + (threadIdx.x >> 7);
    int c4 = threadIdx.x & 127;
    int ml = mlv[b];
    float4 v;
    if (j < ml) {
        int idx = g_idx[b*TM_ + j];
        v = *(const float4*)&h[((size_t)(b*TT_ + idx))*D_ + c4*4];
    } else {
        v = make_float4(0.f, 0.f, 0.f, 0.f);
    }
    *(float4*)&out[((size_t)(b*TM_ + j))*D_ + c4*4] = v;
}

// =================== host launcher ===================
extern "C" void kernel_launch(void* const* d_in, const int* in_sizes, int n_in,
                              void* d_out, int out_size) {
    const float* h_text = (const float*)d_in[0];   // [32,512,512]
    const float* mel    = (const float*)d_in[1];   // [32,80,2048]
    const int*   tl     = (const int*)  d_in[2];   // [32]
    const int*   mlv    = (const int*)  d_in[3];   // [32]
    const float* w_proj = (const float*)d_in[4];   // [512,80]
    const float* b_proj = (const float*)d_in[5];   // [512]
    const float* ldp    = (const float*)d_in[6];   // [32,512]
    float* out = (float*)d_out;

    const int K2_SMEM = (80*132 + 80*129) * 4;        // 83520
    const int K3_SMEM = (64*512 + 512) * 4;           // 133120
    cudaFuncSetAttribute(k2_attn, cudaFuncAttributeMaxDynamicSharedMemorySize, K2_SMEM);
    cudaFuncSetAttribute(k3_dp,   cudaFuncAttributeMaxDynamicSharedMemorySize, K3_SMEM);

    k1_hw<<<256, 256>>>(h_text, w_proj);
    k1_hb<<<2048, 256>>>(h_text, b_proj);
    k2_attn<<<dim3(4, 16, 32), 256, K2_SMEM>>>(mel, tl, mlv);
    k3_dp<<<32, 32, K3_SMEM>>>(ldp, tl, mlv, out);
    k5_expand<<<dim3(1, 1024, 32), 256>>>(h_text, mlv, out);
}